// round 1
// baseline (speedup 1.0000x reference)
#include <cuda_runtime.h>
#include <stdint.h>
#include <math.h>

// Problem dims
#define T_      16384      // B*S tokens
#define D_      1024
#define E_      64
#define NE_     128        // gate + noise logits concatenated
#define NNOISE  1048576    // T_*E_

// Output layout (all float32, tuple order, flattened):
//  [0,           32768)    routing_weights  [T,2]
//  [32768,       65536)    expert_indices   [T,2]  (as float)
//  [65536]                 load_balance_loss
//  [65537,      1114113)   router_probs     [T,64]
//  [1114113]               noise_scale_mean
#define OUT_RW    0
#define OUT_IDX   32768
#define OUT_LOSS  65536
#define OUT_PROBS 65537
#define OUT_NSM   1114113

// Scratch (device globals — no allocation allowed)
__device__ float g_logits[T_ * NE_];   // 8 MB: [t][0..63]=clean, [t][64..127]=noise-lin
__device__ float g_sumprob[E_];
__device__ int   g_tok[E_];
__device__ float g_nssum;

// ---------------------------------------------------------------------------
// Threefry-2x32 (JAX-exact)
// ---------------------------------------------------------------------------
__host__ __device__ __forceinline__ uint32_t rotl32(uint32_t v, int d) {
    return (v << d) | (v >> (32 - d));
}

__host__ __device__ __forceinline__ void tf2x32(uint32_t k0, uint32_t k1,
                                                uint32_t x0, uint32_t x1,
                                                uint32_t& o0, uint32_t& o1) {
    uint32_t ks0 = k0, ks1 = k1, ks2 = 0x1BD11BDAu ^ k0 ^ k1;
    x0 += ks0; x1 += ks1;
    // i=0, set A, inject (ks1, ks2+1)
    x0 += x1; x1 = rotl32(x1, 13); x1 ^= x0;
    x0 += x1; x1 = rotl32(x1, 15); x1 ^= x0;
    x0 += x1; x1 = rotl32(x1, 26); x1 ^= x0;
    x0 += x1; x1 = rotl32(x1,  6); x1 ^= x0;
    x0 += ks1; x1 += ks2 + 1u;
    // i=1, set B, inject (ks2, ks0+2)
    x0 += x1; x1 = rotl32(x1, 17); x1 ^= x0;
    x0 += x1; x1 = rotl32(x1, 29); x1 ^= x0;
    x0 += x1; x1 = rotl32(x1, 16); x1 ^= x0;
    x0 += x1; x1 = rotl32(x1, 24); x1 ^= x0;
    x0 += ks2; x1 += ks0 + 2u;
    // i=2, set A, inject (ks0, ks1+3)
    x0 += x1; x1 = rotl32(x1, 13); x1 ^= x0;
    x0 += x1; x1 = rotl32(x1, 15); x1 ^= x0;
    x0 += x1; x1 = rotl32(x1, 26); x1 ^= x0;
    x0 += x1; x1 = rotl32(x1,  6); x1 ^= x0;
    x0 += ks0; x1 += ks1 + 3u;
    // i=3, set B, inject (ks1, ks2+4)
    x0 += x1; x1 = rotl32(x1, 17); x1 ^= x0;
    x0 += x1; x1 = rotl32(x1, 29); x1 ^= x0;
    x0 += x1; x1 = rotl32(x1, 16); x1 ^= x0;
    x0 += x1; x1 = rotl32(x1, 24); x1 ^= x0;
    x0 += ks1; x1 += ks2 + 4u;
    // i=4, set A, inject (ks2, ks0+5)
    x0 += x1; x1 = rotl32(x1, 13); x1 ^= x0;
    x0 += x1; x1 = rotl32(x1, 15); x1 ^= x0;
    x0 += x1; x1 = rotl32(x1, 26); x1 ^= x0;
    x0 += x1; x1 = rotl32(x1,  6); x1 ^= x0;
    x0 += ks2; x1 += ks0 + 5u;
    o0 = x0; o1 = x1;
}

// XLA's ErfInv (Giles), float32 path — match reference bit-closely
__device__ __forceinline__ float erfinv_xla(float x) {
    float w = -log1pf(-x * x);
    float p;
    if (w < 5.0f) {
        w -= 2.5f;
        p = 2.81022636e-08f;
        p = fmaf(p, w, 3.43273939e-07f);
        p = fmaf(p, w, -3.5233877e-06f);
        p = fmaf(p, w, -4.39150654e-06f);
        p = fmaf(p, w, 0.00021858087f);
        p = fmaf(p, w, -0.00125372503f);
        p = fmaf(p, w, -0.00417768164f);
        p = fmaf(p, w, 0.246640727f);
        p = fmaf(p, w, 1.50140941f);
    } else {
        w = sqrtf(w) - 3.0f;
        p = -0.000200214257f;
        p = fmaf(p, w, 0.000100950558f);
        p = fmaf(p, w, 0.00134934322f);
        p = fmaf(p, w, -0.00367342844f);
        p = fmaf(p, w, 0.00573950773f);
        p = fmaf(p, w, -0.0076224613f);
        p = fmaf(p, w, 0.00943887047f);
        p = fmaf(p, w, 1.00167406f);
        p = fmaf(p, w, 2.83297682f);
    }
    return p * x;
}

// jax.random.normal element i, partitionable threefry: block (hi=0, lo=i), bits=b1^b2
__device__ __forceinline__ float jax_normal(uint32_t k0, uint32_t k1, uint32_t i) {
    uint32_t b1, b2;
    tf2x32(k0, k1, 0u, i, b1, b2);
    uint32_t bits = b1 ^ b2;
    float f = __uint_as_float((bits >> 9) | 0x3F800000u) - 1.0f;  // [0,1)
    const float lo = -0.99999994039535522461f;                    // nextafter(-1,0)
    float u = fmaf(f, 2.0f, lo);                                  // (maxval-minval)=2.0 in f32
    u = fmaxf(u, lo);
    return 1.41421353816986083984f * erfinv_xla(u);               // f32(sqrt(2))
}

__device__ __forceinline__ float softplus_f(float x) {
    // jax.nn.softplus = logaddexp(x, 0) = max(x,0) + log1p(exp(-|x|))
    return fmaxf(x, 0.0f) + log1pf(expf(-fabsf(x)));
}

// ---------------------------------------------------------------------------
// GEMM: C[t, 0..127] = x[t,:] · [W_gate; W_noise]^T    (fp32, tiled SGEMM)
// BM=64, BN=128, BK=16, 128 threads, 8x8 per thread
// ---------------------------------------------------------------------------
__global__ __launch_bounds__(128) void gemm_kernel(const float* __restrict__ X,
                                                   const float* __restrict__ Wg,
                                                   const float* __restrict__ Wn) {
    __shared__ float Xs[16][68];
    __shared__ float Ws[16][132];
    const int m0 = blockIdx.x * 64;
    const int tid = threadIdx.x;                // 0..127
    const int tr = (tid / 16) * 8;              // 0..56
    const int tc = (tid % 16) * 8;              // 0..120
    float acc[8][8];
#pragma unroll
    for (int i = 0; i < 8; i++)
#pragma unroll
        for (int j = 0; j < 8; j++) acc[i][j] = 0.0f;

    for (int k0 = 0; k0 < D_; k0 += 16) {
        // X tile: 64 rows x 16 cols = 256 float4, 2 per thread
#pragma unroll
        for (int it = 0; it < 2; it++) {
            int idx = tid + it * 128;
            int r = idx >> 2;
            int c4 = (idx & 3) * 4;
            float4 v = *(const float4*)(X + (size_t)(m0 + r) * D_ + k0 + c4);
            Xs[c4 + 0][r] = v.x; Xs[c4 + 1][r] = v.y;
            Xs[c4 + 2][r] = v.z; Xs[c4 + 3][r] = v.w;
        }
        // W tile: 128 rows x 16 cols = 512 float4, 4 per thread
#pragma unroll
        for (int it = 0; it < 4; it++) {
            int idx = tid + it * 128;
            int r = idx >> 2;
            int c4 = (idx & 3) * 4;
            const float* wrow = (r < E_) ? (Wg + (size_t)r * D_)
                                         : (Wn + (size_t)(r - E_) * D_);
            float4 v = *(const float4*)(wrow + k0 + c4);
            Ws[c4 + 0][r] = v.x; Ws[c4 + 1][r] = v.y;
            Ws[c4 + 2][r] = v.z; Ws[c4 + 3][r] = v.w;
        }
        __syncthreads();
#pragma unroll
        for (int k = 0; k < 16; k++) {
            float xf[8], wf[8];
            *(float4*)&xf[0] = *(const float4*)&Xs[k][tr];
            *(float4*)&xf[4] = *(const float4*)&Xs[k][tr + 4];
            *(float4*)&wf[0] = *(const float4*)&Ws[k][tc];
            *(float4*)&wf[4] = *(const float4*)&Ws[k][tc + 4];
#pragma unroll
            for (int i = 0; i < 8; i++)
#pragma unroll
                for (int j = 0; j < 8; j++)
                    acc[i][j] = fmaf(xf[i], wf[j], acc[i][j]);
        }
        __syncthreads();
    }
#pragma unroll
    for (int i = 0; i < 8; i++)
#pragma unroll
        for (int j = 0; j < 8; j += 4) {
            float4 v = make_float4(acc[i][j], acc[i][j + 1], acc[i][j + 2], acc[i][j + 3]);
            *(float4*)(g_logits + (size_t)(m0 + tr + i) * NE_ + tc + j) = v;
        }
}

// ---------------------------------------------------------------------------
// Router epilogue: warp per token (8 tokens/block)
// ---------------------------------------------------------------------------
__global__ __launch_bounds__(256) void router_kernel(float* __restrict__ out,
                                                     uint32_t k0, uint32_t k1) {
    __shared__ float s_prob[E_];
    __shared__ int   s_tok[E_];
    __shared__ float s_ns;
    const int tid = threadIdx.x;
    if (tid < E_) { s_prob[tid] = 0.0f; s_tok[tid] = 0; }
    if (tid == 0) s_ns = 0.0f;
    __syncthreads();

    const int warp = tid >> 5, lane = tid & 31;
    const int t = blockIdx.x * 8 + warp;
    const float* row = g_logits + (size_t)t * NE_;

    float c0 = row[lane],      c1 = row[32 + lane];
    float n0 = row[64 + lane], n1 = row[96 + lane];
    float sp0 = softplus_f(n0), sp1 = softplus_f(n1);

    float nv0 = jax_normal(k0, k1, (uint32_t)(t * 64 + lane));
    float nv1 = jax_normal(k0, k1, (uint32_t)(t * 64 + 32 + lane));
    float z0 = c0 + nv0 * sp0;     // NOISE_STD = 1
    float z1 = c1 + nv1 * sp1;

    const unsigned FULL = 0xFFFFFFFFu;

    // softmax over noisy logits
    float m = fmaxf(z0, z1);
#pragma unroll
    for (int off = 16; off; off >>= 1) m = fmaxf(m, __shfl_xor_sync(FULL, m, off));
    float p0 = expf(z0 - m), p1 = expf(z1 - m);
    float s = p0 + p1;
#pragma unroll
    for (int off = 16; off; off >>= 1) s += __shfl_xor_sync(FULL, s, off);
    p0 /= s; p1 /= s;

    // top-1 (ties -> lower index; e0 < e1 always)
    const int e0 = lane, e1 = lane + 32;
    float bv = p0; int bi = e0;
    if (p1 > bv) { bv = p1; bi = e1; }
#pragma unroll
    for (int off = 16; off; off >>= 1) {
        float ov = __shfl_xor_sync(FULL, bv, off);
        int   oi = __shfl_xor_sync(FULL, bi, off);
        if (ov > bv || (ov == bv && oi < bi)) { bv = ov; bi = oi; }
    }
    const float v1 = bv; const int i1 = bi;

    // top-2 (exclude i1)
    float cv0 = (e0 == i1) ? -INFINITY : p0;
    float cv1 = (e1 == i1) ? -INFINITY : p1;
    bv = cv0; bi = e0;
    if (cv1 > bv) { bv = cv1; bi = e1; }
#pragma unroll
    for (int off = 16; off; off >>= 1) {
        float ov = __shfl_xor_sync(FULL, bv, off);
        int   oi = __shfl_xor_sync(FULL, bi, off);
        if (ov > bv || (ov == bv && oi < bi)) { bv = ov; bi = oi; }
    }
    const float v2 = bv; const int i2 = bi;

    // softmax over clean logits -> router_probs
    float mc = fmaxf(c0, c1);
#pragma unroll
    for (int off = 16; off; off >>= 1) mc = fmaxf(mc, __shfl_xor_sync(FULL, mc, off));
    float q0 = expf(c0 - mc), q1 = expf(c1 - mc);
    float sc = q0 + q1;
#pragma unroll
    for (int off = 16; off; off >>= 1) sc += __shfl_xor_sync(FULL, sc, off);
    q0 /= sc; q1 /= sc;

    out[OUT_PROBS + (size_t)t * E_ + lane]      = q0;
    out[OUT_PROBS + (size_t)t * E_ + 32 + lane] = q1;

    // noise-scale partial sum
    float ns = sp0 + sp1;
#pragma unroll
    for (int off = 16; off; off >>= 1) ns += __shfl_xor_sync(FULL, ns, off);

    if (lane == 0) {
        float sw = v1 + v2;
        out[OUT_RW  + t * 2 + 0] = v1 / sw;
        out[OUT_RW  + t * 2 + 1] = v2 / sw;
        out[OUT_IDX + t * 2 + 0] = (float)i1;
        out[OUT_IDX + t * 2 + 1] = (float)i2;
        atomicAdd(&s_tok[i1], 1);
        atomicAdd(&s_tok[i2], 1);
        atomicAdd(&s_ns, ns);
    }
    atomicAdd(&s_prob[lane],      q0);
    atomicAdd(&s_prob[lane + 32], q1);

    __syncthreads();
    if (tid < E_) {
        atomicAdd(&g_sumprob[tid], s_prob[tid]);
        atomicAdd(&g_tok[tid], s_tok[tid]);
    }
    if (tid == 0) atomicAdd(&g_nssum, s_ns);
}

__global__ void init_kernel() {
    int i = threadIdx.x;
    if (i < E_) { g_sumprob[i] = 0.0f; g_tok[i] = 0; }
    if (i == 0) g_nssum = 0.0f;
}

__global__ void finalize_kernel(float* __restrict__ out) {
    __shared__ float sh[E_];
    int e = threadIdx.x;
    sh[e] = ((float)g_tok[e] / (float)T_) * (g_sumprob[e] / (float)T_);
    __syncthreads();
    if (e == 0) {
        float acc = 0.0f;
        for (int i = 0; i < E_; i++) acc += sh[i];
        out[OUT_LOSS] = 0.01f * 64.0f * acc;
        out[OUT_NSM]  = g_nssum / (float)NNOISE;
    }
}

// ---------------------------------------------------------------------------
extern "C" void kernel_launch(void* const* d_in, const int* in_sizes, int n_in,
                              void* d_out, int out_size) {
    const float* x  = (const float*)d_in[0];
    const float* Wg = (const float*)d_in[1];
    const float* Wn = (const float*)d_in[2];
    float* out = (float*)d_out;

    // NOISE_KEY = fold_in(key(0), 12345) = threefry2x32([0,0], [0,12345])
    uint32_t nk0, nk1;
    tf2x32(0u, 0u, 0u, 12345u, nk0, nk1);

    init_kernel<<<1, 64>>>();
    gemm_kernel<<<T_ / 64, 128>>>(x, Wg, Wn);
    router_kernel<<<T_ / 8, 256>>>(out, nk0, nk1);
    finalize_kernel<<<1, 64>>>(out);
}